// round 13
// baseline (speedup 1.0000x reference)
#include <cuda_runtime.h>
#include <cstdint>
#include <cstddef>

// Problem shape (fixed by the reference):
//   v_feat: (B=32, N=16, T=256, D=512) fp32
//   t_feat: (C=512, D=512) fp32
//   split : int scalar (nonzero -> normalize)
//   out   : (B, C, T) fp32 = einsum('btd,cd->bct', mean_n(norm(v)), norm(t)) / 0.07
#define BB 32
#define NN 16
#define TT 256
#define DD 512
#define CC 512
#define MTOT (BB * TT)

#define BM 64                 // rows of v_mean per CTA
#define PITCH_A 516           // As row pitch (floats); 516%32=4 -> conflict-free frags
#define BNT 256               // n-tile width in phase 2
#define PITCH_B 36            // Bs row pitch
#define NKT (DD / 32)         // 16 k-tiles
#define SMEM_FLOATS (BM * PITCH_A + 2 * BNT * PITCH_B)
#define SMEM_BYTES  (SMEM_FLOATS * 4)

// Scratch (device global: allocation inside kernel_launch is forbidden)
__device__ float g_tnorm[CC * DD];     // 1 MB

__device__ __forceinline__ float tf32_rna(float x) {
    unsigned u;
    asm("cvt.rna.tf32.f32 %0, %1;" : "=r"(u) : "f"(x));
    return __uint_as_float(u);
}

__device__ __forceinline__ void mma_tf32(float* c, const unsigned* a, const unsigned* b) {
    asm volatile(
        "mma.sync.aligned.m16n8k8.row.col.f32.tf32.tf32.f32 "
        "{%0,%1,%2,%3}, {%4,%5,%6,%7}, {%8,%9}, {%0,%1,%2,%3};\n"
        : "+f"(c[0]), "+f"(c[1]), "+f"(c[2]), "+f"(c[3])
        : "r"(a[0]), "r"(a[1]), "r"(a[2]), "r"(a[3]), "r"(b[0]), "r"(b[1]));
}

// ---------------------------------------------------------------------------
// Kernel A: normalize t_feat rows, tf32-round (unchanged, verified).
// ---------------------------------------------------------------------------
__global__ void __launch_bounds__(256) norm_t_kernel(const float* __restrict__ tfeat,
                                                     const int* __restrict__ split) {
    const int w    = (blockIdx.x * 256 + threadIdx.x) >> 5;   // row c, 0..511
    const int lane = threadIdx.x & 31;
    const bool donorm = (*split != 0);

    const float4* r = reinterpret_cast<const float4*>(tfeat + (size_t)w * DD);
    float4 x0 = r[lane], x1 = r[lane + 32], x2 = r[lane + 64], x3 = r[lane + 96];

    float ss = x0.x * x0.x + x0.y * x0.y + x0.z * x0.z + x0.w * x0.w
             + x1.x * x1.x + x1.y * x1.y + x1.z * x1.z + x1.w * x1.w
             + x2.x * x2.x + x2.y * x2.y + x2.z * x2.z + x2.w * x2.w
             + x3.x * x3.x + x3.y * x3.y + x3.z * x3.z + x3.w * x3.w;
#pragma unroll
    for (int off = 16; off > 0; off >>= 1)
        ss += __shfl_xor_sync(0xffffffffu, ss, off);

    float inv = donorm ? (1.0f / fmaxf(sqrtf(ss), 1e-12f)) : 1.0f;

    float4* o = reinterpret_cast<float4*>(g_tnorm + (size_t)w * DD);
    float4 y;
    y.x = tf32_rna(x0.x * inv); y.y = tf32_rna(x0.y * inv);
    y.z = tf32_rna(x0.z * inv); y.w = tf32_rna(x0.w * inv); o[lane]      = y;
    y.x = tf32_rna(x1.x * inv); y.y = tf32_rna(x1.y * inv);
    y.z = tf32_rna(x1.z * inv); y.w = tf32_rna(x1.w * inv); o[lane + 32] = y;
    y.x = tf32_rna(x2.x * inv); y.y = tf32_rna(x2.y * inv);
    y.z = tf32_rna(x2.z * inv); y.w = tf32_rna(x2.w * inv); o[lane + 64] = y;
    y.x = tf32_rna(x3.x * inv); y.y = tf32_rna(x3.y * inv);
    y.z = tf32_rna(x3.z * inv); y.w = tf32_rna(x3.w * inv); o[lane + 96] = y;
}

// ---------------------------------------------------------------------------
// Kernel B: FUSED. 128 CTAs x 256 threads, one wave.
// Phase 1: each warp computes 8 v_mean rows (normalize 16 n-rows, mean,
//          tf32-round) directly into smem As[64][516]. Software-pipelined:
//          n+1's loads issue before n's reduction chain.
// Phase 2: round-6-proven mma structure. 8 warps as 2(m) x 4(n), warp tile
//          32x64, BK=32, B tiles [256][32] double-buffered with register
//          prefetch and ONE barrier per k-iteration. A is smem-resident.
// ---------------------------------------------------------------------------
__global__ void __launch_bounds__(256) fused_kernel(const float* __restrict__ v,
                                                    const int* __restrict__ split,
                                                    float* __restrict__ out) {
    extern __shared__ float smem[];
    float* As = smem;                       // [BM][PITCH_A]
    float* Bs = smem + BM * PITCH_A;        // [2][BNT][PITCH_B]

    const int tid  = threadIdx.x;
    const int wid  = tid >> 5;              // 0..7
    const int lane = tid & 31;
    const int gid  = lane >> 2;             // 0..7
    const int tig  = lane & 3;              // 0..3

    const int mbase = blockIdx.x * BM;      // 0..8128
    const int bB    = mbase >> 8;           // batch, constant per CTA
    const int tb    = mbase & 255;          // t offset of this block
    const bool donorm = (*split != 0);

    // ---------------- Phase 1: v_mean rows -> As ----------------
#pragma unroll 1
    for (int j = 0; j < BM / 8; j++) {
        const int row = wid * 8 + j;                       // 0..63
        const int t   = tb + row;
        const float* rowp = v + ((size_t)bB * NN * TT + t) * DD;  // n-stride TT*DD

        float4 x0, x1, x2, x3, y0, y1, y2, y3;
        {
            const float4* p = reinterpret_cast<const float4*>(rowp);
            x0 = p[lane]; x1 = p[lane + 32]; x2 = p[lane + 64]; x3 = p[lane + 96];
        }
        float4 a0 = make_float4(0.f, 0.f, 0.f, 0.f);
        float4 a1 = a0, a2 = a0, a3 = a0;

#pragma unroll
        for (int n = 0; n < NN; n++) {
            if (n + 1 < NN) {   // prefetch next n-row while we reduce this one
                const float4* q = reinterpret_cast<const float4*>(rowp + (size_t)(n + 1) * (TT * DD));
                y0 = q[lane]; y1 = q[lane + 32]; y2 = q[lane + 64]; y3 = q[lane + 96];
            }
            float ss = x0.x * x0.x + x0.y * x0.y + x0.z * x0.z + x0.w * x0.w
                     + x1.x * x1.x + x1.y * x1.y + x1.z * x1.z + x1.w * x1.w
                     + x2.x * x2.x + x2.y * x2.y + x2.z * x2.z + x2.w * x2.w
                     + x3.x * x3.x + x3.y * x3.y + x3.z * x3.z + x3.w * x3.w;
#pragma unroll
            for (int off = 16; off > 0; off >>= 1)
                ss += __shfl_xor_sync(0xffffffffu, ss, off);

            float inv = donorm ? (1.0f / fmaxf(sqrtf(ss), 1e-12f)) : 1.0f;

            a0.x = fmaf(x0.x, inv, a0.x); a0.y = fmaf(x0.y, inv, a0.y);
            a0.z = fmaf(x0.z, inv, a0.z); a0.w = fmaf(x0.w, inv, a0.w);
            a1.x = fmaf(x1.x, inv, a1.x); a1.y = fmaf(x1.y, inv, a1.y);
            a1.z = fmaf(x1.z, inv, a1.z); a1.w = fmaf(x1.w, inv, a1.w);
            a2.x = fmaf(x2.x, inv, a2.x); a2.y = fmaf(x2.y, inv, a2.y);
            a2.z = fmaf(x2.z, inv, a2.z); a2.w = fmaf(x2.w, inv, a2.w);
            a3.x = fmaf(x3.x, inv, a3.x); a3.y = fmaf(x3.y, inv, a3.y);
            a3.z = fmaf(x3.z, inv, a3.z); a3.w = fmaf(x3.w, inv, a3.w);

            x0 = y0; x1 = y1; x2 = y2; x3 = y3;
        }

        const float sc = 1.0f / 16.0f;
        float* ar = As + (size_t)row * PITCH_A;
        float4 w;
        w.x = tf32_rna(a0.x * sc); w.y = tf32_rna(a0.y * sc);
        w.z = tf32_rna(a0.z * sc); w.w = tf32_rna(a0.w * sc);
        *reinterpret_cast<float4*>(ar + lane * 4)       = w;
        w.x = tf32_rna(a1.x * sc); w.y = tf32_rna(a1.y * sc);
        w.z = tf32_rna(a1.z * sc); w.w = tf32_rna(a1.w * sc);
        *reinterpret_cast<float4*>(ar + 128 + lane * 4) = w;
        w.x = tf32_rna(a2.x * sc); w.y = tf32_rna(a2.y * sc);
        w.z = tf32_rna(a2.z * sc); w.w = tf32_rna(a2.w * sc);
        *reinterpret_cast<float4*>(ar + 256 + lane * 4) = w;
        w.x = tf32_rna(a3.x * sc); w.y = tf32_rna(a3.y * sc);
        w.z = tf32_rna(a3.z * sc); w.w = tf32_rna(a3.w * sc);
        *reinterpret_cast<float4*>(ar + 384 + lane * 4) = w;
    }
    __syncthreads();   // As fully built

    // ---------------- Phase 2: GEMM on resident A ----------------
    const int wm = (wid & 1) * 32;     // 2 warp-rows cover BM=64
    const int wn = (wid >> 1) * 64;    // 4 warp-cols cover BNT=256

    // B staging coordinates: 8 float4 per thread per k-tile (256 rows x 32 cols)
    int brow[8], bcol[8];
#pragma unroll
    for (int i = 0; i < 8; i++) {
        int idx = tid + i * 256;       // 0..2047
        brow[i] = idx >> 3;            // 0..255
        bcol[i] = (idx & 7) * 4;       // 0..28
    }

    const float s = 1.0f / 0.07f;
    float* ob = out + (size_t)bB * (CC * TT) + tb;

#pragma unroll 1
    for (int nt = 0; nt < 2; nt++) {
        const int nbase = nt * BNT;
        const float* Bg = g_tnorm + (size_t)nbase * DD;

        float c[2][8][4];
#pragma unroll
        for (int mc = 0; mc < 2; mc++)
#pragma unroll
            for (int nc = 0; nc < 8; nc++)
#pragma unroll
                for (int i = 0; i < 4; i++) c[mc][nc][i] = 0.f;

        float4 bv[8];
        // Prologue: k-tile 0 -> Bs buf 0. The barrier also joins any warps
        // still finishing the previous nt (protects Bs buf1 reuse at it=0).
#pragma unroll
        for (int i = 0; i < 8; i++)
            bv[i] = *reinterpret_cast<const float4*>(Bg + (size_t)brow[i] * DD + bcol[i]);
#pragma unroll
        for (int i = 0; i < 8; i++)
            *reinterpret_cast<float4*>(&Bs[(size_t)brow[i] * PITCH_B + bcol[i]]) = bv[i];
        __syncthreads();

        for (int it = 0; it < NKT; it++) {
            const int buf = it & 1;
            const bool more = (it + 1 < NKT);
            if (more) {
                const int k0 = (it + 1) * 32;
#pragma unroll
                for (int i = 0; i < 8; i++)
                    bv[i] = *reinterpret_cast<const float4*>(Bg + (size_t)brow[i] * DD + k0 + bcol[i]);
            }

            const float* Bb = Bs + (size_t)buf * (BNT * PITCH_B);
            const int kbase = it * 32;
#pragma unroll
            for (int k8 = 0; k8 < 4; k8++) {
                const int koA = kbase + k8 * 8;   // A col in full-K smem tile
                const int koB = k8 * 8;           // B col within k-tile
                unsigned a[2][4], bf[8][2];
#pragma unroll
                for (int mc = 0; mc < 2; mc++) {
                    int r0 = wm + mc * 16 + gid;
                    a[mc][0] = __float_as_uint(As[(size_t)r0 * PITCH_A + koA + tig]);
                    a[mc][1] = __float_as_uint(As[(size_t)(r0 + 8) * PITCH_A + koA + tig]);
                    a[mc][2] = __float_as_uint(As[(size_t)r0 * PITCH_A + koA + tig + 4]);
                    a[mc][3] = __float_as_uint(As[(size_t)(r0 + 8) * PITCH_A + koA + tig + 4]);
                }
#pragma unroll
                for (int nc = 0; nc < 8; nc++) {
                    int rn = wn + nc * 8 + gid;
                    bf[nc][0] = __float_as_uint(Bb[(size_t)rn * PITCH_B + koB + tig]);
                    bf[nc][1] = __float_as_uint(Bb[(size_t)rn * PITCH_B + koB + tig + 4]);
                }
#pragma unroll
                for (int mc = 0; mc < 2; mc++)
#pragma unroll
                    for (int nc = 0; nc < 8; nc++)
                        mma_tf32(c[mc][nc], a[mc], bf[nc]);
            }

            if (more) {
#pragma unroll
                for (int i = 0; i < 8; i++)
                    *reinterpret_cast<float4*>(&Bs[(size_t)(buf ^ 1) * (BNT * PITCH_B)
                                                   + (size_t)brow[i] * PITCH_B + bcol[i]]) = bv[i];
                __syncthreads();
            }
        }

        // Epilogue for this n-tile: out[b, c, t]
#pragma unroll
        for (int mc = 0; mc < 2; mc++) {
#pragma unroll
            for (int nc = 0; nc < 8; nc++) {
                int m0 = wm + mc * 16 + gid;
                int n0 = nbase + wn + nc * 8 + 2 * tig;
                ob[(size_t)n0 * TT + m0]           = c[mc][nc][0] * s;
                ob[(size_t)(n0 + 1) * TT + m0]     = c[mc][nc][1] * s;
                ob[(size_t)n0 * TT + m0 + 8]       = c[mc][nc][2] * s;
                ob[(size_t)(n0 + 1) * TT + m0 + 8] = c[mc][nc][3] * s;
            }
        }
    }
}

// ---------------------------------------------------------------------------
extern "C" void kernel_launch(void* const* d_in, const int* in_sizes, int n_in,
                              void* d_out, int out_size) {
    const float* v     = (const float*)d_in[0];
    const float* tfeat = (const float*)d_in[1];
    const int*   split = (const int*)d_in[2];
    float*       out   = (float*)d_out;

    // Host-side attribute set: no alloc, no sync, capture-safe.
    cudaFuncSetAttribute(fused_kernel, cudaFuncAttributeMaxDynamicSharedMemorySize,
                         SMEM_BYTES);

    norm_t_kernel<<<CC / 8, 256>>>(tfeat, split);                 // 512 warps
    fused_kernel<<<MTOT / BM, 256, SMEM_BYTES>>>(v, split, out);  // 128 CTAs, one wave
}

// round 14
// speedup vs baseline: 1.3705x; 1.3705x over previous
#include <cuda_runtime.h>
#include <cstdint>
#include <cstddef>

// Problem shape (fixed by the reference):
//   v_feat: (B=32, N=16, T=256, D=512) fp32
//   t_feat: (C=512, D=512) fp32
//   split : int scalar (nonzero -> normalize)
//   out   : (B, C, T) fp32 = einsum('btd,cd->bct', mean_n(norm(v)), norm(t)) / 0.07
#define BB 32
#define NN 16
#define TT 256
#define DD 512
#define CC 512
#define MTOT (BB * TT)            // 8192 rows of v_mean

// Scratch (device globals: allocation inside kernel_launch is forbidden)
__device__ float g_vmean[MTOT * DD];   // 16 MB
__device__ float g_tnorm[CC * DD];     // 1 MB

__device__ __forceinline__ float tf32_rna(float x) {
    unsigned u;
    asm("cvt.rna.tf32.f32 %0, %1;" : "=r"(u) : "f"(x));
    return __uint_as_float(u);
}

// ---------------------------------------------------------------------------
// Kernel 1: per-(b,t) warp: normalize each of the 16 n-rows (L2 over d),
// accumulate, divide by 16, tf32-round, store v_mean row. Pure shfl reduce.
// (Round-6 exact: 45.3us @ 78.6% DRAM — at the traffic floor. Do not touch.)
// ---------------------------------------------------------------------------
__global__ void __launch_bounds__(256) reduce_v_kernel(const float* __restrict__ v,
                                                       const int* __restrict__ split) {
    const int w    = (blockIdx.x * 256 + threadIdx.x) >> 5;   // (b,t) index, 0..8191
    const int lane = threadIdx.x & 31;
    const bool donorm = (*split != 0);

    const int b = w >> 8;
    const int t = w & 255;
    const float* vb = v + (((size_t)b * NN) * TT + t) * DD;

    float4 acc0 = make_float4(0.f, 0.f, 0.f, 0.f);
    float4 acc1 = acc0, acc2 = acc0, acc3 = acc0;

#pragma unroll
    for (int n = 0; n < NN; n++) {
        const float4* r = reinterpret_cast<const float4*>(vb + (size_t)n * (TT * DD));
        float4 x0 = r[lane];
        float4 x1 = r[lane + 32];
        float4 x2 = r[lane + 64];
        float4 x3 = r[lane + 96];

        float ss = x0.x * x0.x + x0.y * x0.y + x0.z * x0.z + x0.w * x0.w
                 + x1.x * x1.x + x1.y * x1.y + x1.z * x1.z + x1.w * x1.w
                 + x2.x * x2.x + x2.y * x2.y + x2.z * x2.z + x2.w * x2.w
                 + x3.x * x3.x + x3.y * x3.y + x3.z * x3.z + x3.w * x3.w;
#pragma unroll
        for (int off = 16; off > 0; off >>= 1)
            ss += __shfl_xor_sync(0xffffffffu, ss, off);

        float inv = donorm ? (1.0f / fmaxf(sqrtf(ss), 1e-12f)) : 1.0f;

        acc0.x = fmaf(x0.x, inv, acc0.x); acc0.y = fmaf(x0.y, inv, acc0.y);
        acc0.z = fmaf(x0.z, inv, acc0.z); acc0.w = fmaf(x0.w, inv, acc0.w);
        acc1.x = fmaf(x1.x, inv, acc1.x); acc1.y = fmaf(x1.y, inv, acc1.y);
        acc1.z = fmaf(x1.z, inv, acc1.z); acc1.w = fmaf(x1.w, inv, acc1.w);
        acc2.x = fmaf(x2.x, inv, acc2.x); acc2.y = fmaf(x2.y, inv, acc2.y);
        acc2.z = fmaf(x2.z, inv, acc2.z); acc2.w = fmaf(x2.w, inv, acc2.w);
        acc3.x = fmaf(x3.x, inv, acc3.x); acc3.y = fmaf(x3.y, inv, acc3.y);
        acc3.z = fmaf(x3.z, inv, acc3.z); acc3.w = fmaf(x3.w, inv, acc3.w);
    }

    const float sc = 1.0f / 16.0f;
    float4* o = reinterpret_cast<float4*>(g_vmean + (size_t)w * DD);
    float4 y;
    y.x = tf32_rna(acc0.x * sc); y.y = tf32_rna(acc0.y * sc);
    y.z = tf32_rna(acc0.z * sc); y.w = tf32_rna(acc0.w * sc); o[lane]      = y;
    y.x = tf32_rna(acc1.x * sc); y.y = tf32_rna(acc1.y * sc);
    y.z = tf32_rna(acc1.z * sc); y.w = tf32_rna(acc1.w * sc); o[lane + 32] = y;
    y.x = tf32_rna(acc2.x * sc); y.y = tf32_rna(acc2.y * sc);
    y.z = tf32_rna(acc2.z * sc); y.w = tf32_rna(acc2.w * sc); o[lane + 64] = y;
    y.x = tf32_rna(acc3.x * sc); y.y = tf32_rna(acc3.y * sc);
    y.z = tf32_rna(acc3.z * sc); y.w = tf32_rna(acc3.w * sc); o[lane + 96] = y;
}

// ---------------------------------------------------------------------------
// Kernel 2: normalize t_feat rows, tf32-round. (Round-6 exact.)
// ---------------------------------------------------------------------------
__global__ void __launch_bounds__(256) norm_t_kernel(const float* __restrict__ tfeat,
                                                     const int* __restrict__ split) {
    const int w    = (blockIdx.x * 256 + threadIdx.x) >> 5;   // row c, 0..511
    const int lane = threadIdx.x & 31;
    const bool donorm = (*split != 0);

    const float4* r = reinterpret_cast<const float4*>(tfeat + (size_t)w * DD);
    float4 x0 = r[lane], x1 = r[lane + 32], x2 = r[lane + 64], x3 = r[lane + 96];

    float ss = x0.x * x0.x + x0.y * x0.y + x0.z * x0.z + x0.w * x0.w
             + x1.x * x1.x + x1.y * x1.y + x1.z * x1.z + x1.w * x1.w
             + x2.x * x2.x + x2.y * x2.y + x2.z * x2.z + x2.w * x2.w
             + x3.x * x3.x + x3.y * x3.y + x3.z * x3.z + x3.w * x3.w;
#pragma unroll
    for (int off = 16; off > 0; off >>= 1)
        ss += __shfl_xor_sync(0xffffffffu, ss, off);

    float inv = donorm ? (1.0f / fmaxf(sqrtf(ss), 1e-12f)) : 1.0f;

    float4* o = reinterpret_cast<float4*>(g_tnorm + (size_t)w * DD);
    float4 y;
    y.x = tf32_rna(x0.x * inv); y.y = tf32_rna(x0.y * inv);
    y.z = tf32_rna(x0.z * inv); y.w = tf32_rna(x0.w * inv); o[lane]      = y;
    y.x = tf32_rna(x1.x * inv); y.y = tf32_rna(x1.y * inv);
    y.z = tf32_rna(x1.z * inv); y.w = tf32_rna(x1.w * inv); o[lane + 32] = y;
    y.x = tf32_rna(x2.x * inv); y.y = tf32_rna(x2.y * inv);
    y.z = tf32_rna(x2.z * inv); y.w = tf32_rna(x2.w * inv); o[lane + 64] = y;
    y.x = tf32_rna(x3.x * inv); y.y = tf32_rna(x3.y * inv);
    y.z = tf32_rna(x3.z * inv); y.w = tf32_rna(x3.w * inv); o[lane + 96] = y;
}

// ---------------------------------------------------------------------------
// Kernel 3: tf32 GEMM, ONE-WAVE variant of the round-6 design.
// Block tile BM=128 x BN=256, BK=32, 512 threads / 16 warps as 4(m) x 4(n);
// each warp runs the EXACT round-6 32x64 tile inner code (same fragment maps,
// same LDS:mma ratio, same register-prefetch double buffer, one barrier/iter).
// Grid = (512/256) x (8192/128) = 2 x 64 = 128 CTAs -> single wave on 148 SMs
// (round-6 had 256 CTAs = 2 waves; wave-2 latency exposure was the overhead).
// Dynamic smem: 2*(128+256)*36*4 = 110.6 KB.
// ---------------------------------------------------------------------------
__device__ __forceinline__ void mma_tf32(float* c, const unsigned* a, const unsigned* b) {
    asm volatile(
        "mma.sync.aligned.m16n8k8.row.col.f32.tf32.tf32.f32 "
        "{%0,%1,%2,%3}, {%4,%5,%6,%7}, {%8,%9}, {%0,%1,%2,%3};\n"
        : "+f"(c[0]), "+f"(c[1]), "+f"(c[2]), "+f"(c[3])
        : "r"(a[0]), "r"(a[1]), "r"(a[2]), "r"(a[3]), "r"(b[0]), "r"(b[1]));
}

#define NKT   (DD / 32)           // 16 K-tiles
#define BM    128
#define BN    256
#define PIT   36                  // smem row pitch (floats)
#define A_BUF (BM * PIT)          // 4608 floats per A buffer
#define B_BUF (BN * PIT)          // 9216 floats per B buffer
#define GSMEM ((2 * A_BUF + 2 * B_BUF) * 4)   // 110592 bytes

__global__ void __launch_bounds__(512) gemm_kernel(float* __restrict__ out) {
    extern __shared__ float sm[];
    float* As = sm;                    // [2][BM][PIT]
    float* Bs = sm + 2 * A_BUF;        // [2][BN][PIT]

    const int tid  = threadIdx.x;
    const int wid  = tid >> 5;         // 0..15
    const int lane = tid & 31;
    const int gid  = lane >> 2;        // 0..7
    const int tig  = lane & 3;         // 0..3
    const int wm   = (wid & 3) * 32;   // 4 m-warps cover BM=128
    const int wn   = (wid >> 2) * 64;  // 4 n-warps cover BN=256
    const int mbase = blockIdx.y * BM;
    const int nbase = blockIdx.x * BN;

    // Staging coordinates. A: 1024 float4 over 512 thr -> 2 each.
    //                      B: 2048 float4 over 512 thr -> 4 each.
    int arow[2], acol[2], brow[4], bcol[4];
#pragma unroll
    for (int i = 0; i < 2; i++) {
        int idx = tid + i * 512;       // 0..1023
        arow[i] = idx >> 3;            // 0..127
        acol[i] = (idx & 7) * 4;
    }
#pragma unroll
    for (int i = 0; i < 4; i++) {
        int idx = tid + i * 512;       // 0..2047
        brow[i] = idx >> 3;            // 0..255
        bcol[i] = (idx & 7) * 4;
    }

    float c[2][8][4];
#pragma unroll
    for (int mc = 0; mc < 2; mc++)
#pragma unroll
        for (int nc = 0; nc < 8; nc++)
#pragma unroll
            for (int i = 0; i < 4; i++) c[mc][nc][i] = 0.f;

    const float* Ag = g_vmean + (size_t)mbase * DD;
    const float* Bg = g_tnorm + (size_t)nbase * DD;

    float4 av[2], bv[4];

    // Prologue: K-tile 0 -> buffer 0
#pragma unroll
    for (int i = 0; i < 2; i++)
        av[i] = *reinterpret_cast<const float4*>(Ag + (size_t)arow[i] * DD + acol[i]);
#pragma unroll
    for (int i = 0; i < 4; i++)
        bv[i] = *reinterpret_cast<const float4*>(Bg + (size_t)brow[i] * DD + bcol[i]);
#pragma unroll
    for (int i = 0; i < 2; i++)
        *reinterpret_cast<float4*>(&As[(size_t)arow[i] * PIT + acol[i]]) = av[i];
#pragma unroll
    for (int i = 0; i < 4; i++)
        *reinterpret_cast<float4*>(&Bs[(size_t)brow[i] * PIT + bcol[i]]) = bv[i];
    __syncthreads();

    for (int it = 0; it < NKT; it++) {
        const int buf = it & 1;
        const bool more = (it + 1 < NKT);

        if (more) {   // register prefetch of the next K-tile (round-6 proven)
            const int k0 = (it + 1) * 32;
#pragma unroll
            for (int i = 0; i < 2; i++)
                av[i] = *reinterpret_cast<const float4*>(Ag + (size_t)arow[i] * DD + k0 + acol[i]);
#pragma unroll
            for (int i = 0; i < 4; i++)
                bv[i] = *reinterpret_cast<const float4*>(Bg + (size_t)brow[i] * DD + k0 + bcol[i]);
        }

        const float* Ab = As + (size_t)buf * A_BUF;
        const float* Bb = Bs + (size_t)buf * B_BUF;

#pragma unroll
        for (int k8 = 0; k8 < 4; k8++) {
            const int ko = k8 * 8;
            unsigned a[2][4], bf[8][2];
#pragma unroll
            for (int mc = 0; mc < 2; mc++) {
                int r0 = wm + mc * 16 + gid;
                a[mc][0] = __float_as_uint(Ab[(size_t)r0 * PIT + ko + tig]);
                a[mc][1] = __float_as_uint(Ab[(size_t)(r0 + 8) * PIT + ko + tig]);
                a[mc][2] = __float_as_uint(Ab[(size_t)r0 * PIT + ko + tig + 4]);
                a[mc][3] = __float_as_uint(Ab[(size_t)(r0 + 8) * PIT + ko + tig + 4]);
            }
#pragma unroll
            for (int nc = 0; nc < 8; nc++) {
                int rn = wn + nc * 8 + gid;
                bf[nc][0] = __float_as_uint(Bb[(size_t)rn * PIT + ko + tig]);
                bf[nc][1] = __float_as_uint(Bb[(size_t)rn * PIT + ko + tig + 4]);
            }
#pragma unroll
            for (int mc = 0; mc < 2; mc++)
#pragma unroll
                for (int nc = 0; nc < 8; nc++)
                    mma_tf32(c[mc][nc], a[mc], bf[nc]);
        }

        if (more) {
            float* An = As + (size_t)(buf ^ 1) * A_BUF;
            float* Bn = Bs + (size_t)(buf ^ 1) * B_BUF;
#pragma unroll
            for (int i = 0; i < 2; i++)
                *reinterpret_cast<float4*>(&An[(size_t)arow[i] * PIT + acol[i]]) = av[i];
#pragma unroll
            for (int i = 0; i < 4; i++)
                *reinterpret_cast<float4*>(&Bn[(size_t)brow[i] * PIT + bcol[i]]) = bv[i];
            __syncthreads();
        }
    }

    // Epilogue: out[b, c, t], m = b*256+t. Per-block b is constant (BM=128).
    const float s  = 1.0f / 0.07f;
    const int   bB = mbase >> 8;
    const int   tb = mbase & 255;
    float* ob = out + (size_t)bB * (CC * TT) + tb;

#pragma unroll
    for (int mc = 0; mc < 2; mc++) {
#pragma unroll
        for (int nc = 0; nc < 8; nc++) {
            int m0 = wm + mc * 16 + gid;
            int n0 = nbase + wn + nc * 8 + 2 * tig;
            ob[(size_t)n0 * TT + m0]           = c[mc][nc][0] * s;
            ob[(size_t)(n0 + 1) * TT + m0]     = c[mc][nc][1] * s;
            ob[(size_t)n0 * TT + m0 + 8]       = c[mc][nc][2] * s;
            ob[(size_t)(n0 + 1) * TT + m0 + 8] = c[mc][nc][3] * s;
        }
    }
}

// ---------------------------------------------------------------------------
extern "C" void kernel_launch(void* const* d_in, const int* in_sizes, int n_in,
                              void* d_out, int out_size) {
    const float* v     = (const float*)d_in[0];
    const float* tfeat = (const float*)d_in[1];
    const int*   split = (const int*)d_in[2];
    float*       out   = (float*)d_out;

    // Host attribute set: no alloc, no sync — capture-safe.
    cudaFuncSetAttribute(gemm_kernel, cudaFuncAttributeMaxDynamicSharedMemorySize,
                         GSMEM);

    reduce_v_kernel<<<MTOT / 8, 256>>>(v, split);       // 8192 warps (BW phase)
    norm_t_kernel<<<CC / 8, 256>>>(tfeat, split);       // 512 warps
    gemm_kernel<<<dim3(CC / BN, MTOT / BM), 512, GSMEM>>>(out);  // 128 CTAs, 1 wave
}